// round 11
// baseline (speedup 1.0000x reference)
#include <cuda_runtime.h>
#include <cuda_bf16.h>
#include <cstdint>
#include <math.h>

#define NB   8192
#define FST  257

typedef unsigned long long ull;

// ---------------- device scratch ----------------
__device__ unsigned g_m1[NB * 8];
__device__ unsigned g_m2[NB * 8];
__device__ float    g_f[NB * 64];
__device__ __nv_bfloat16 g_A1b[64 * 256];   // bf16(W3) [o][i]
__device__ __nv_bfloat16 g_B1T[256 * 256];  // [j][i] = W2[i][j]
__device__ __nv_bfloat16 g_B2T[256 * 256];  // [d][j] = W1[j][d]

// ---------------- helpers ----------------
static __device__ __forceinline__ uint32_t smem_u32(const void* p) {
    uint32_t a;
    asm("{ .reg .u64 t; cvta.to.shared.u64 t, %1; cvt.u32.u64 %0, t; }" : "=r"(a) : "l"(p));
    return a;
}
#define CP_ASYNC16(dst, src) asm volatile("cp.async.cg.shared.global [%0], [%1], 16;" :: "r"(dst), "l"(src) : "memory")
#define CP_COMMIT()          asm volatile("cp.async.commit_group;" ::: "memory")
#define CP_WAIT(n)           asm volatile("cp.async.wait_group %0;" :: "n"(n) : "memory")
#define LDSM_X4(r0, r1, r2, r3, addr) \
    asm volatile("ldmatrix.sync.aligned.m8n8.x4.shared.b16 {%0,%1,%2,%3}, [%4];" \
        : "=r"(r0), "=r"(r1), "=r"(r2), "=r"(r3) : "r"(addr))

static __device__ __forceinline__ void mma_bf16(float* c, uint32_t a0, uint32_t a1,
                                                uint32_t a2, uint32_t a3,
                                                uint32_t b0, uint32_t b1) {
    asm volatile("mma.sync.aligned.m16n8k16.row.col.f32.bf16.bf16.f32 "
        "{%0,%1,%2,%3}, {%4,%5,%6,%7}, {%8,%9}, {%0,%1,%2,%3};"
        : "+f"(c[0]), "+f"(c[1]), "+f"(c[2]), "+f"(c[3])
        : "r"(a0), "r"(a1), "r"(a2), "r"(a3), "r"(b0), "r"(b1));
}

// ---------------- prep: bf16 operand images ----------------
__global__ void __launch_bounds__(256)
prep_kernel(const float* __restrict__ W1, const float* __restrict__ W2,
            const float* __restrict__ W3)
{
    const int t0 = blockIdx.x * 256 + threadIdx.x;
    for (int e = t0; e < 65536; e += 64 * 256) {
        int r = e >> 8, c = e & 255;
        g_B1T[e] = __float2bfloat16(W2[(size_t)c * 256 + r]);   // [j=r][i=c] = W2[i][j]
        g_B2T[e] = __float2bfloat16(W1[(size_t)c * 256 + r]);   // [d=r][j=c] = W1[j][d]
    }
    for (int e = t0; e < 16384; e += 64 * 256)
        g_A1b[e] = __float2bfloat16(W3[e]);
}

// ---------------- forward: 3-layer MLP + masks (proven) ----------------
__global__ void __launch_bounds__(256, 1)
fwd_kernel(const float* __restrict__ x,
           const float* __restrict__ W1, const float* __restrict__ b1,
           const float* __restrict__ W2, const float* __restrict__ b2,
           const float* __restrict__ W3, const float* __restrict__ b3)
{
    extern __shared__ float sm[];
    float* bufA = sm;
    float* bufB = bufA + 64 * FST;
    float* wt   = bufB + 64 * FST;
    const int tid = threadIdx.x;
    const int s0 = blockIdx.x * 64;
    const int tx = tid & 15, ty = tid >> 4;

    for (int e = tid; e < 64 * 64; e += 256) {
        int r = e >> 6, c = e & 63;
        float4 v = reinterpret_cast<const float4*>(x)[(size_t)(s0 + r) * 64 + c];
        float* d = &bufA[r * FST + c * 4];
        d[0] = v.x; d[1] = v.y; d[2] = v.z; d[3] = v.w;
    }
    __syncthreads();

    const float* Ws[3] = {W1, W2, W3};
    const float* bs[3] = {b1, b2, b3};
    float* ib = bufA;
    float* ob = bufB;

    for (int L = 0; L < 3; L++) {
        const int HO = (L == 2) ? 64 : 256;
        for (int oc = 0; oc < HO / 64; oc++) {
            __syncthreads();
            for (int e = tid; e < 64 * 64; e += 256) {
                int r = e >> 6, c = e & 63;
                float4 v = reinterpret_cast<const float4*>(Ws[L])[(size_t)(oc * 64 + r) * 64 + c];
                float* d = &wt[r * FST + c * 4];
                d[0] = v.x; d[1] = v.y; d[2] = v.z; d[3] = v.w;
            }
            __syncthreads();

            float acc[4][4];
            #pragma unroll
            for (int u = 0; u < 4; u++) {
                float bv = bs[L][oc * 64 + tx + 16 * u];
                #pragma unroll
                for (int i = 0; i < 4; i++) acc[i][u] = bv;
            }
            #pragma unroll 4
            for (int k = 0; k < 256; k++) {
                float a[4], bv[4];
                #pragma unroll
                for (int i = 0; i < 4; i++) a[i] = ib[(ty * 4 + i) * FST + k];
                #pragma unroll
                for (int u = 0; u < 4; u++) bv[u] = wt[(tx + 16 * u) * FST + k];
                #pragma unroll
                for (int i = 0; i < 4; i++)
                    #pragma unroll
                    for (int u = 0; u < 4; u++)
                        acc[i][u] = fmaf(a[i], bv[u], acc[i][u]);
            }
            if (L < 2) {
                #pragma unroll
                for (int i = 0; i < 4; i++)
                    #pragma unroll
                    for (int u = 0; u < 4; u++)
                        ob[(ty * 4 + i) * FST + oc * 64 + tx + 16 * u] = fmaxf(acc[i][u], 0.f);
            } else {
                #pragma unroll
                for (int i = 0; i < 4; i++)
                    #pragma unroll
                    for (int u = 0; u < 4; u++)
                        g_f[(size_t)(s0 + ty * 4 + i) * 64 + tx + 16 * u] = acc[i][u];
            }
        }
        if (L < 2) {
            __syncthreads();
            unsigned* mg = L ? g_m2 : g_m1;
            for (int e = tid; e < 64 * 8; e += 256) {
                int s = e >> 3, w = e & 7;
                unsigned bits = 0;
                for (int bb = 0; bb < 32; bb++)
                    if (ob[s * FST + w * 32 + bb] > 0.f) bits |= 1u << bb;
                mg[(size_t)(s0 + s) * 8 + w] = bits;
            }
            float* t = ib; ib = ob; ob = t;
            __syncthreads();
        }
    }
}

// ---------------- mma.sync bf16 Jacobian kernel (ldmatrix + cp.async pipeline) ----------------
// CTA b: samples 2b, 2b+1 (M=128). GEMM1: Bt = A1(masked W3) @ W2 ; A2 = bf16(mask_m1(Bt));
// GEMM2: H = A2 @ W1 ; q_s = ||H_s||^2 ; out = tanh(softplus(k) f / (sqrt(q)+1e-4)).
#define AS_ST 264
#define BS_ST 136
#define AS_OFF 0
#define B0_OFF 67584
#define B1_OFF 137216
#define MS_OFF 206848
#define JAC_SMEM 207104

__global__ void __launch_bounds__(256, 1)
jacmma_kernel(const float* __restrict__ kp, float* __restrict__ out)
{
    extern __shared__ char smc[];
    __nv_bfloat16* As = (__nv_bfloat16*)(smc + AS_OFF);
    unsigned* m1w = (unsigned*)(smc + MS_OFF);
    unsigned* m2w = m1w + 16;
    float* red = (float*)(m2w + 16);
    float* qv  = red + 8;

    const int tid = threadIdx.x;
    const int w = tid >> 5, lane = tid & 31;
    const int g = lane >> 2, tg = lane & 3;
    const int b = blockIdx.x;
    const int mw = (w >> 2) * 64, nw = (w & 3) * 64;
    const int s = w >> 2;
    const uint32_t sA = smem_u32(As);
    const uint32_t sB0 = smem_u32(smc + B0_OFF);
    const uint32_t sB1 = smem_u32(smc + B1_OFF);

    // ldmatrix per-lane offsets: tile = lane>>3, row = lane&7
    const int tile = lane >> 3, row = lane & 7;
    const uint32_t aLane = sA + (uint32_t)(((mw + (tile & 1) * 8 + row) * AS_ST
                                           + (tile >> 1) * 8) * 2);
    const uint32_t bLane = (uint32_t)(((nw + (tile >> 1) * 8 + row) * BS_ST
                                      + (tile & 1) * 8) * 2);

    if (tid < 16) {
        m1w[tid] = g_m1[(size_t)(2 * b + (tid >> 3)) * 8 + (tid & 7)];
        m2w[tid] = g_m2[(size_t)(2 * b + (tid >> 3)) * 8 + (tid & 7)];
    }

    // ---- stage chunk 0 & 1 (GEMM1 B, kc=0/1) ----
    {
        const char* src0 = (const char*)(g_B1T + (size_t)tid * 256);
        uint32_t d0 = sB0 + (uint32_t)(tid * BS_ST) * 2;
        #pragma unroll
        for (int u2 = 0; u2 < 8; u2++) CP_ASYNC16(d0 + u2 * 32, src0 + u2 * 32);
        #pragma unroll
        for (int u2 = 0; u2 < 8; u2++) CP_ASYNC16(d0 + 16 + u2 * 32, src0 + 16 + u2 * 32);
        CP_COMMIT();
        const char* src1 = src0 + 256;
        uint32_t d1 = sB1 + (uint32_t)(tid * BS_ST) * 2;
        #pragma unroll
        for (int u2 = 0; u2 < 16; u2++) CP_ASYNC16(d1 + u2 * 16, src1 + u2 * 16);
        CP_COMMIT();
    }

    // ---- A1 = masked bf16(W3) ----
    for (int u = tid; u < 16384; u += 256) {
        int m = u >> 7, i = (u & 127) * 2;
        int ss = m >> 6, o = m & 63;
        unsigned bits = (m2w[ss * 8 + (i >> 5)] >> (i & 31)) & 3u;
        unsigned v = *(const unsigned*)&g_A1b[o * 256 + i];
        if (!(bits & 1)) v &= 0xFFFF0000u;
        if (!(bits & 2)) v &= 0x0000FFFFu;
        *(unsigned*)&As[m * AS_ST + i] = v;
    }

    float c[4][8][4];
    #pragma unroll
    for (int mt = 0; mt < 4; mt++)
        #pragma unroll
        for (int nt = 0; nt < 8; nt++)
            #pragma unroll
            for (int e = 0; e < 4; e++) c[mt][nt][e] = 0.f;

    // compute one k-chunk (128 k) against B buffer `bb`, A at k-offset kc*128
    auto compute = [&](uint32_t bb, int kc) {
        #pragma unroll
        for (int ks = 0; ks < 8; ks++) {
            const int kk = ks * 16;
            uint32_t bf[8][2];
            #pragma unroll
            for (int p = 0; p < 4; p++)
                LDSM_X4(bf[2 * p][0], bf[2 * p][1], bf[2 * p + 1][0], bf[2 * p + 1][1],
                        bb + bLane + (uint32_t)((p * 16 * BS_ST + kk) * 2));
            #pragma unroll
            for (int mt = 0; mt < 4; mt++) {
                uint32_t a0, a1, a2, a3;
                LDSM_X4(a0, a1, a2, a3,
                        aLane + (uint32_t)((mt * 16 * AS_ST + kc * 128 + kk) * 2));
                #pragma unroll
                for (int nt = 0; nt < 8; nt++)
                    mma_bf16(c[mt][nt], a0, a1, a2, a3, bf[nt][0], bf[nt][1]);
            }
        }
    };

    // ================== GEMM1 ==================
    CP_WAIT(1);
    __syncthreads();               // chunk0 ready; A1 build complete
    compute(sB0, 0);
    __syncthreads();               // all warps done with buf0
    {   // stage chunk 2 (GEMM2 B, kc=0) into buf0
        const char* src = (const char*)(g_B2T + (size_t)tid * 256);
        uint32_t d0 = sB0 + (uint32_t)(tid * BS_ST) * 2;
        #pragma unroll
        for (int u2 = 0; u2 < 16; u2++) CP_ASYNC16(d0 + u2 * 16, src + u2 * 16);
        CP_COMMIT();
    }
    CP_WAIT(1);
    __syncthreads();               // chunk1 ready
    compute(sB1, 1);
    __syncthreads();               // all warps done with buf1 + GEMM1 accums final
    {   // stage chunk 3 (GEMM2 B, kc=1) into buf1
        const char* src = (const char*)(g_B2T + (size_t)tid * 256 + 128);
        uint32_t d1 = sB1 + (uint32_t)(tid * BS_ST) * 2;
        #pragma unroll
        for (int u2 = 0; u2 < 16; u2++) CP_ASYNC16(d1 + u2 * 16, src + u2 * 16);
        CP_COMMIT();
    }

    // ---- A2 = bf16(mask_m1(Bt)) -> As (overlaps chunk3 flight) ----
    #pragma unroll
    for (int mt = 0; mt < 4; mt++) {
        const int r0 = mw + mt * 16 + g;
        #pragma unroll
        for (int nt = 0; nt < 8; nt++) {
            const int j0 = nw + nt * 8 + tg * 2;
            const unsigned word = m1w[s * 8 + (j0 >> 5)];
            const bool k0 = (word >> (j0 & 31)) & 1u;
            const bool k1 = (word >> ((j0 & 31) + 1)) & 1u;
            float* cc = c[mt][nt];
            unsigned lo0 = (unsigned)__bfloat16_as_ushort(__float2bfloat16(k0 ? cc[0] : 0.f));
            unsigned hi0 = (unsigned)__bfloat16_as_ushort(__float2bfloat16(k1 ? cc[1] : 0.f));
            *(unsigned*)&As[r0 * AS_ST + j0] = lo0 | (hi0 << 16);
            unsigned lo1 = (unsigned)__bfloat16_as_ushort(__float2bfloat16(k0 ? cc[2] : 0.f));
            unsigned hi1 = (unsigned)__bfloat16_as_ushort(__float2bfloat16(k1 ? cc[3] : 0.f));
            *(unsigned*)&As[(r0 + 8) * AS_ST + j0] = lo1 | (hi1 << 16);
        }
    }
    #pragma unroll
    for (int mt = 0; mt < 4; mt++)
        #pragma unroll
        for (int nt = 0; nt < 8; nt++)
            #pragma unroll
            for (int e = 0; e < 4; e++) c[mt][nt][e] = 0.f;

    // ================== GEMM2 ==================
    CP_WAIT(1);
    __syncthreads();               // chunk2 ready; A2 writes visible
    compute(sB0, 0);
    CP_WAIT(0);
    __syncthreads();               // chunk3 ready
    compute(sB1, 1);

    // ---- q reduction ----
    float q = 0.f;
    #pragma unroll
    for (int mt = 0; mt < 4; mt++)
        #pragma unroll
        for (int nt = 0; nt < 8; nt++)
            #pragma unroll
            for (int e = 0; e < 4; e++)
                q = fmaf(c[mt][nt][e], c[mt][nt][e], q);
    #pragma unroll
    for (int sft = 16; sft; sft >>= 1) q += __shfl_xor_sync(0xFFFFFFFFu, q, sft);
    if (lane == 0) red[w] = q;
    __syncthreads();
    if (tid < 2)
        qv[tid] = red[tid * 4] + red[tid * 4 + 1] + red[tid * 4 + 2] + red[tid * 4 + 3];
    __syncthreads();
    if (tid < 128) {
        int ss = tid >> 6, o = tid & 63;
        float fv = g_f[(size_t)(2 * b + ss) * 64 + o];
        float kk = kp[0];
        float sp = (kk > 20.f) ? kk : log1pf(expf(kk));
        out[(size_t)(2 * b + ss) * 64 + o] = tanhf(sp * fv / (sqrtf(qv[ss]) + 1e-4f));
    }
}

extern "C" void kernel_launch(void* const* d_in, const int* in_sizes, int n_in,
                              void* d_out, int out_size) {
    const float* x  = (const float*)d_in[0];
    const float* W1 = (const float*)d_in[1];
    const float* b1 = (const float*)d_in[2];
    const float* W2 = (const float*)d_in[3];
    const float* b2 = (const float*)d_in[4];
    const float* W3 = (const float*)d_in[5];
    const float* b3 = (const float*)d_in[6];
    const float* k  = (const float*)d_in[7];
    float* out = (float*)d_out;

    const size_t sm_fwd = 3 * 64 * FST * sizeof(float);
    cudaFuncSetAttribute(fwd_kernel, cudaFuncAttributeMaxDynamicSharedMemorySize, (int)sm_fwd);
    cudaFuncSetAttribute(jacmma_kernel, cudaFuncAttributeMaxDynamicSharedMemorySize, JAC_SMEM);

    prep_kernel<<<64, 256>>>(W1, W2, W3);
    fwd_kernel<<<128, 256, sm_fwd>>>(x, W1, b1, W2, b2, W3, b3);
    jacmma_kernel<<<NB / 2, 256, JAC_SMEM>>>(k, out);
}

// round 12
// speedup vs baseline: 1.2331x; 1.2331x over previous
#include <cuda_runtime.h>
#include <cuda_bf16.h>
#include <cstdint>
#include <math.h>

#define NB   8192
#define FST  257

typedef unsigned long long ull;

// ---------------- device scratch ----------------
__device__ unsigned g_m1[NB * 8];
__device__ unsigned g_m2[NB * 8];
__device__ float    g_f[NB * 64];
__device__ __nv_bfloat16 g_A1b[64 * 256];   // bf16(W3) [o][i]
__device__ __nv_bfloat16 g_B1T[256 * 256];  // [j][i] = W2[i][j]
__device__ __nv_bfloat16 g_B2T[256 * 256];  // [d][j] = W1[j][d]

// ---------------- helpers ----------------
static __device__ __forceinline__ uint32_t smem_u32(const void* p) {
    uint32_t a;
    asm("{ .reg .u64 t; cvta.to.shared.u64 t, %1; cvt.u32.u64 %0, t; }" : "=r"(a) : "l"(p));
    return a;
}
#define CP_ASYNC16(dst, src) asm volatile("cp.async.cg.shared.global [%0], [%1], 16;" :: "r"(dst), "l"(src) : "memory")
#define CP_COMMIT()          asm volatile("cp.async.commit_group;" ::: "memory")
#define CP_WAIT(n)           asm volatile("cp.async.wait_group %0;" :: "n"(n) : "memory")

static __device__ __forceinline__ void mma_bf16(float* c, uint32_t a0, uint32_t a1,
                                                uint32_t a2, uint32_t a3,
                                                uint32_t b0, uint32_t b1) {
    asm volatile("mma.sync.aligned.m16n8k16.row.col.f32.bf16.bf16.f32 "
        "{%0,%1,%2,%3}, {%4,%5,%6,%7}, {%8,%9}, {%0,%1,%2,%3};"
        : "+f"(c[0]), "+f"(c[1]), "+f"(c[2]), "+f"(c[3])
        : "r"(a0), "r"(a1), "r"(a2), "r"(a3), "r"(b0), "r"(b1));
}

// ---------------- prep: bf16 operand images ----------------
__global__ void __launch_bounds__(256)
prep_kernel(const float* __restrict__ W1, const float* __restrict__ W2,
            const float* __restrict__ W3)
{
    const int t0 = blockIdx.x * 256 + threadIdx.x;
    for (int e = t0; e < 65536; e += 64 * 256) {
        int r = e >> 8, c = e & 255;
        g_B1T[e] = __float2bfloat16(W2[(size_t)c * 256 + r]);   // [j=r][i=c] = W2[i][j]
        g_B2T[e] = __float2bfloat16(W1[(size_t)c * 256 + r]);   // [d=r][j=c] = W1[j][d]
    }
    for (int e = t0; e < 16384; e += 64 * 256)
        g_A1b[e] = __float2bfloat16(W3[e]);
}

// ---------------- forward: 3-layer MLP + masks (proven) ----------------
__global__ void __launch_bounds__(256, 1)
fwd_kernel(const float* __restrict__ x,
           const float* __restrict__ W1, const float* __restrict__ b1,
           const float* __restrict__ W2, const float* __restrict__ b2,
           const float* __restrict__ W3, const float* __restrict__ b3)
{
    extern __shared__ float sm[];
    float* bufA = sm;
    float* bufB = bufA + 64 * FST;
    float* wt   = bufB + 64 * FST;
    const int tid = threadIdx.x;
    const int s0 = blockIdx.x * 64;
    const int tx = tid & 15, ty = tid >> 4;

    for (int e = tid; e < 64 * 64; e += 256) {
        int r = e >> 6, c = e & 63;
        float4 v = reinterpret_cast<const float4*>(x)[(size_t)(s0 + r) * 64 + c];
        float* d = &bufA[r * FST + c * 4];
        d[0] = v.x; d[1] = v.y; d[2] = v.z; d[3] = v.w;
    }
    __syncthreads();

    const float* Ws[3] = {W1, W2, W3};
    const float* bs[3] = {b1, b2, b3};
    float* ib = bufA;
    float* ob = bufB;

    for (int L = 0; L < 3; L++) {
        const int HO = (L == 2) ? 64 : 256;
        for (int oc = 0; oc < HO / 64; oc++) {
            __syncthreads();
            for (int e = tid; e < 64 * 64; e += 256) {
                int r = e >> 6, c = e & 63;
                float4 v = reinterpret_cast<const float4*>(Ws[L])[(size_t)(oc * 64 + r) * 64 + c];
                float* d = &wt[r * FST + c * 4];
                d[0] = v.x; d[1] = v.y; d[2] = v.z; d[3] = v.w;
            }
            __syncthreads();

            float acc[4][4];
            #pragma unroll
            for (int u = 0; u < 4; u++) {
                float bv = bs[L][oc * 64 + tx + 16 * u];
                #pragma unroll
                for (int i = 0; i < 4; i++) acc[i][u] = bv;
            }
            #pragma unroll 4
            for (int k = 0; k < 256; k++) {
                float a[4], bv[4];
                #pragma unroll
                for (int i = 0; i < 4; i++) a[i] = ib[(ty * 4 + i) * FST + k];
                #pragma unroll
                for (int u = 0; u < 4; u++) bv[u] = wt[(tx + 16 * u) * FST + k];
                #pragma unroll
                for (int i = 0; i < 4; i++)
                    #pragma unroll
                    for (int u = 0; u < 4; u++)
                        acc[i][u] = fmaf(a[i], bv[u], acc[i][u]);
            }
            if (L < 2) {
                #pragma unroll
                for (int i = 0; i < 4; i++)
                    #pragma unroll
                    for (int u = 0; u < 4; u++)
                        ob[(ty * 4 + i) * FST + oc * 64 + tx + 16 * u] = fmaxf(acc[i][u], 0.f);
            } else {
                #pragma unroll
                for (int i = 0; i < 4; i++)
                    #pragma unroll
                    for (int u = 0; u < 4; u++)
                        g_f[(size_t)(s0 + ty * 4 + i) * 64 + tx + 16 * u] = acc[i][u];
            }
        }
        if (L < 2) {
            __syncthreads();
            unsigned* mg = L ? g_m2 : g_m1;
            for (int e = tid; e < 64 * 8; e += 256) {
                int s = e >> 3, w = e & 7;
                unsigned bits = 0;
                for (int bb = 0; bb < 32; bb++)
                    if (ob[s * FST + w * 32 + bb] > 0.f) bits |= 1u << bb;
                mg[(size_t)(s0 + s) * 8 + w] = bits;
            }
            float* t = ib; ib = ob; ob = t;
            __syncthreads();
        }
    }
}

// ---------------- mma.sync bf16 Jacobian kernel, 2 CTAs/SM ----------------
// CTA b: samples 2b, 2b+1 (A rows 0-63 = sample0, 64-127 = sample1).
// Each GEMM runs as 2 M-passes (pass p = sample p, 64 rows, full N=256, full K=256).
// Warp tile M32 x N64 -> 64 accumulator regs. After GEMM1 pass p, sample p's A1
// rows are dead; masked-bf16 A2 rows overwrite them in place.
// B staged in k32 chunks, double-buffered cp.async.
// Chunk schedule: t=0..31 -> gemm=t>>4, pass=(t>>3)&1, kchunk=t&7.
#define AS_ST 264
#define BS_ST 40
#define AS_OFF 0
#define B0_OFF 67584
#define B1_OFF 88064
#define MS_OFF 108544
#define JAC_SMEM 108800

__global__ void __launch_bounds__(256, 2)
jacmma_kernel(const float* __restrict__ kp, float* __restrict__ out)
{
    extern __shared__ char smc[];
    __nv_bfloat16* As = (__nv_bfloat16*)(smc + AS_OFF);
    unsigned* m1w = (unsigned*)(smc + MS_OFF);
    unsigned* m2w = m1w + 16;
    float* red = (float*)(m2w + 16);
    float* qv  = red + 8;

    const int tid = threadIdx.x;
    const int w = tid >> 5, lane = tid & 31;
    const int g = lane >> 2, tg = lane & 3;
    const int b = blockIdx.x;
    const int mwp = (w >> 2) * 32;      // m offset within the 64-row pass
    const int nw  = (w & 3) * 64;       // n offset (N=256)
    const uint32_t sBuf[2] = { smem_u32(smc + B0_OFF), smem_u32(smc + B1_OFF) };

    if (tid < 16) {
        m1w[tid] = g_m1[(size_t)(2 * b + (tid >> 3)) * 8 + (tid & 7)];
        m2w[tid] = g_m2[(size_t)(2 * b + (tid >> 3)) * 8 + (tid & 7)];
    }

    // stage one k32 chunk: 256 rows x 64B, one row per thread
    auto stage = [&](int t) {
        const __nv_bfloat16* tab = (t >> 4) ? g_B2T : g_B1T;
        const int ch = t & 7;
        const char* src = (const char*)tab + (size_t)tid * 512 + ch * 64;
        uint32_t dst = sBuf[t & 1] + (uint32_t)tid * 80;
        CP_ASYNC16(dst,      src);
        CP_ASYNC16(dst + 16, src + 16);
        CP_ASYNC16(dst + 32, src + 32);
        CP_ASYNC16(dst + 48, src + 48);
        CP_COMMIT();
    };

    stage(0);

    // ---- A1 = masked bf16(W3) (R8-proven loop) ----
    for (int u = tid; u < 16384; u += 256) {
        int m = u >> 7, i = (u & 127) * 2;
        int ss = m >> 6, o = m & 63;
        unsigned bits = (m2w[ss * 8 + (i >> 5)] >> (i & 31)) & 3u;
        unsigned v = *(const unsigned*)&g_A1b[o * 256 + i];
        if (!(bits & 1)) v &= 0xFFFF0000u;
        if (!(bits & 2)) v &= 0x0000FFFFu;
        *(unsigned*)&As[m * AS_ST + i] = v;
    }

    float c[2][8][4];
    #pragma unroll
    for (int mt = 0; mt < 2; mt++)
        #pragma unroll
        for (int nt = 0; nt < 8; nt++)
            #pragma unroll
            for (int e = 0; e < 4; e++) c[mt][nt][e] = 0.f;

    #pragma unroll 1
    for (int t = 0; t < 32; t++) {
        const int gemm = t >> 4;
        const int p = (t >> 3) & 1;
        const int ch = t & 7;

        if (t < 31) stage(t + 1);
        if (t < 31) { CP_WAIT(1); } else { CP_WAIT(0); }
        __syncthreads();

        const uint32_t bb = sBuf[t & 1];
        const int arow = p * 64 + mwp;
        #pragma unroll
        for (int ks = 0; ks < 2; ks++) {
            const int kk = ch * 32 + ks * 16;
            uint32_t bf[8][2];
            #pragma unroll
            for (int nt = 0; nt < 8; nt++) {
                uint32_t bp = bb + (uint32_t)(((nw + nt * 8 + g) * BS_ST + ks * 16 + tg * 2) * 2);
                asm volatile("ld.shared.u32 %0, [%1];" : "=r"(bf[nt][0]) : "r"(bp));
                asm volatile("ld.shared.u32 %0, [%1];" : "=r"(bf[nt][1]) : "r"(bp + 16));
            }
            #pragma unroll
            for (int mt = 0; mt < 2; mt++) {
                const __nv_bfloat16* ap = &As[(arow + mt * 16 + g) * AS_ST + kk + tg * 2];
                uint32_t a0 = *(const uint32_t*)ap;
                uint32_t a1 = *(const uint32_t*)(ap + 8 * AS_ST);
                uint32_t a2 = *(const uint32_t*)(ap + 8);
                uint32_t a3 = *(const uint32_t*)(ap + 8 * AS_ST + 8);
                #pragma unroll
                for (int nt = 0; nt < 8; nt++)
                    mma_bf16(c[mt][nt], a0, a1, a2, a3, bf[nt][0], bf[nt][1]);
            }
        }
        __syncthreads();

        if (ch == 7) {
            if (gemm == 0) {
                // convert pass-p Bt -> masked bf16 A2, in place over sample p's A1 rows
                #pragma unroll
                for (int mt = 0; mt < 2; mt++) {
                    const int r0 = p * 64 + mwp + mt * 16 + g;
                    #pragma unroll
                    for (int nt = 0; nt < 8; nt++) {
                        const int j0 = nw + nt * 8 + tg * 2;
                        const unsigned word = m1w[p * 8 + (j0 >> 5)];
                        const bool k0 = (word >> (j0 & 31)) & 1u;
                        const bool k1 = (word >> ((j0 & 31) + 1)) & 1u;
                        float* cc = c[mt][nt];
                        unsigned lo0 = (unsigned)__bfloat16_as_ushort(__float2bfloat16(k0 ? cc[0] : 0.f));
                        unsigned hi0 = (unsigned)__bfloat16_as_ushort(__float2bfloat16(k1 ? cc[1] : 0.f));
                        *(unsigned*)&As[r0 * AS_ST + j0] = lo0 | (hi0 << 16);
                        unsigned lo1 = (unsigned)__bfloat16_as_ushort(__float2bfloat16(k0 ? cc[2] : 0.f));
                        unsigned hi1 = (unsigned)__bfloat16_as_ushort(__float2bfloat16(k1 ? cc[3] : 0.f));
                        *(unsigned*)&As[(r0 + 8) * AS_ST + j0] = lo1 | (hi1 << 16);
                    }
                }
            } else {
                // q reduction for sample p
                float q = 0.f;
                #pragma unroll
                for (int mt = 0; mt < 2; mt++)
                    #pragma unroll
                    for (int nt = 0; nt < 8; nt++)
                        #pragma unroll
                        for (int e = 0; e < 4; e++)
                            q = fmaf(c[mt][nt][e], c[mt][nt][e], q);
                #pragma unroll
                for (int sft = 16; sft; sft >>= 1) q += __shfl_xor_sync(0xFFFFFFFFu, q, sft);
                if (lane == 0) red[w] = q;
                __syncthreads();
                if (tid == 0) {
                    float tq = 0.f;
                    for (int i = 0; i < 8; i++) tq += red[i];
                    qv[p] = tq;
                }
            }
            // zero accumulators for next pass
            #pragma unroll
            for (int mt = 0; mt < 2; mt++)
                #pragma unroll
                for (int nt = 0; nt < 8; nt++)
                    #pragma unroll
                    for (int e = 0; e < 4; e++) c[mt][nt][e] = 0.f;
        }
    }

    __syncthreads();
    if (tid < 128) {
        int ss = tid >> 6, o = tid & 63;
        float fv = g_f[(size_t)(2 * b + ss) * 64 + o];
        float kk = kp[0];
        float sp = (kk > 20.f) ? kk : log1pf(expf(kk));
        out[(size_t)(2 * b + ss) * 64 + o] = tanhf(sp * fv / (sqrtf(qv[ss]) + 1e-4f));
    }
}

extern "C" void kernel_launch(void* const* d_in, const int* in_sizes, int n_in,
                              void* d_out, int out_size) {
    const float* x  = (const float*)d_in[0];
    const float* W1 = (const float*)d_in[1];
    const float* b1 = (const float*)d_in[2];
    const float* W2 = (const float*)d_in[3];
    const float* b2 = (const float*)d_in[4];
    const float* W3 = (const float*)d_in[5];
    const float* b3 = (const float*)d_in[6];
    const float* k  = (const float*)d_in[7];
    float* out = (float*)d_out;

    const size_t sm_fwd = 3 * 64 * FST * sizeof(float);
    cudaFuncSetAttribute(fwd_kernel, cudaFuncAttributeMaxDynamicSharedMemorySize, (int)sm_fwd);
    cudaFuncSetAttribute(jacmma_kernel, cudaFuncAttributeMaxDynamicSharedMemorySize, JAC_SMEM);

    prep_kernel<<<64, 256>>>(W1, W2, W3);
    fwd_kernel<<<128, 256, sm_fwd>>>(x, W1, b1, W2, b2, W3, b3);
    jacmma_kernel<<<NB / 2, 256, JAC_SMEM>>>(k, out);
}

// round 13
// speedup vs baseline: 1.5336x; 1.2437x over previous
#include <cuda_runtime.h>
#include <cuda_bf16.h>
#include <cstdint>
#include <math.h>

#define NB   8192
#define FST  257

typedef unsigned long long ull;

// ---------------- device scratch ----------------
__device__ unsigned g_m1[NB * 8];
__device__ unsigned g_m2[NB * 8];
__device__ float    g_f[NB * 64];
__device__ __nv_bfloat16 g_A1b[64 * 256];   // bf16(W3) [o][i]
__device__ __nv_bfloat16 g_B1T[256 * 256];  // [j][i] = W2[i][j]
__device__ __nv_bfloat16 g_B2T[256 * 256];  // [d][j] = W1[j][d]

// ---------------- helpers ----------------
static __device__ __forceinline__ uint32_t smem_u32(const void* p) {
    uint32_t a;
    asm("{ .reg .u64 t; cvta.to.shared.u64 t, %1; cvt.u32.u64 %0, t; }" : "=r"(a) : "l"(p));
    return a;
}
#define CP_ASYNC16(dst, src) asm volatile("cp.async.cg.shared.global [%0], [%1], 16;" :: "r"(dst), "l"(src) : "memory")
#define CP_COMMIT()          asm volatile("cp.async.commit_group;" ::: "memory")
#define CP_WAIT(n)           asm volatile("cp.async.wait_group %0;" :: "n"(n) : "memory")

static __device__ __forceinline__ void mma_bf16(float* c, uint32_t a0, uint32_t a1,
                                                uint32_t a2, uint32_t a3,
                                                uint32_t b0, uint32_t b1) {
    asm volatile("mma.sync.aligned.m16n8k16.row.col.f32.bf16.bf16.f32 "
        "{%0,%1,%2,%3}, {%4,%5,%6,%7}, {%8,%9}, {%0,%1,%2,%3};"
        : "+f"(c[0]), "+f"(c[1]), "+f"(c[2]), "+f"(c[3])
        : "r"(a0), "r"(a1), "r"(a2), "r"(a3), "r"(b0), "r"(b1));
}

// ---------------- prep: bf16 operand images ----------------
__global__ void __launch_bounds__(256)
prep_kernel(const float* __restrict__ W1, const float* __restrict__ W2,
            const float* __restrict__ W3)
{
    const int t0 = blockIdx.x * 256 + threadIdx.x;
    for (int e = t0; e < 65536; e += 64 * 256) {
        int r = e >> 8, c = e & 255;
        g_B1T[e] = __float2bfloat16(W2[(size_t)c * 256 + r]);   // [j=r][i=c] = W2[i][j]
        g_B2T[e] = __float2bfloat16(W1[(size_t)c * 256 + r]);   // [d=r][j=c] = W1[j][d]
    }
    for (int e = t0; e < 16384; e += 64 * 256)
        g_A1b[e] = __float2bfloat16(W3[e]);
}

// ---------------- forward: 3-layer MLP + masks (proven) ----------------
__global__ void __launch_bounds__(256, 1)
fwd_kernel(const float* __restrict__ x,
           const float* __restrict__ W1, const float* __restrict__ b1,
           const float* __restrict__ W2, const float* __restrict__ b2,
           const float* __restrict__ W3, const float* __restrict__ b3)
{
    extern __shared__ float sm[];
    float* bufA = sm;
    float* bufB = bufA + 64 * FST;
    float* wt   = bufB + 64 * FST;
    const int tid = threadIdx.x;
    const int s0 = blockIdx.x * 64;
    const int tx = tid & 15, ty = tid >> 4;

    for (int e = tid; e < 64 * 64; e += 256) {
        int r = e >> 6, c = e & 63;
        float4 v = reinterpret_cast<const float4*>(x)[(size_t)(s0 + r) * 64 + c];
        float* d = &bufA[r * FST + c * 4];
        d[0] = v.x; d[1] = v.y; d[2] = v.z; d[3] = v.w;
    }
    __syncthreads();

    const float* Ws[3] = {W1, W2, W3};
    const float* bs[3] = {b1, b2, b3};
    float* ib = bufA;
    float* ob = bufB;

    for (int L = 0; L < 3; L++) {
        const int HO = (L == 2) ? 64 : 256;
        for (int oc = 0; oc < HO / 64; oc++) {
            __syncthreads();
            for (int e = tid; e < 64 * 64; e += 256) {
                int r = e >> 6, c = e & 63;
                float4 v = reinterpret_cast<const float4*>(Ws[L])[(size_t)(oc * 64 + r) * 64 + c];
                float* d = &wt[r * FST + c * 4];
                d[0] = v.x; d[1] = v.y; d[2] = v.z; d[3] = v.w;
            }
            __syncthreads();

            float acc[4][4];
            #pragma unroll
            for (int u = 0; u < 4; u++) {
                float bv = bs[L][oc * 64 + tx + 16 * u];
                #pragma unroll
                for (int i = 0; i < 4; i++) acc[i][u] = bv;
            }
            #pragma unroll 4
            for (int k = 0; k < 256; k++) {
                float a[4], bv[4];
                #pragma unroll
                for (int i = 0; i < 4; i++) a[i] = ib[(ty * 4 + i) * FST + k];
                #pragma unroll
                for (int u = 0; u < 4; u++) bv[u] = wt[(tx + 16 * u) * FST + k];
                #pragma unroll
                for (int i = 0; i < 4; i++)
                    #pragma unroll
                    for (int u = 0; u < 4; u++)
                        acc[i][u] = fmaf(a[i], bv[u], acc[i][u]);
            }
            if (L < 2) {
                #pragma unroll
                for (int i = 0; i < 4; i++)
                    #pragma unroll
                    for (int u = 0; u < 4; u++)
                        ob[(ty * 4 + i) * FST + oc * 64 + tx + 16 * u] = fmaxf(acc[i][u], 0.f);
            } else {
                #pragma unroll
                for (int i = 0; i < 4; i++)
                    #pragma unroll
                    for (int u = 0; u < 4; u++)
                        g_f[(size_t)(s0 + ty * 4 + i) * 64 + tx + 16 * u] = acc[i][u];
            }
        }
        if (L < 2) {
            __syncthreads();
            unsigned* mg = L ? g_m2 : g_m1;
            for (int e = tid; e < 64 * 8; e += 256) {
                int s = e >> 3, w = e & 7;
                unsigned bits = 0;
                for (int bb = 0; bb < 32; bb++)
                    if (ob[s * FST + w * 32 + bb] > 0.f) bits |= 1u << bb;
                mg[(size_t)(s0 + s) * 8 + w] = bits;
            }
            float* t = ib; ib = ob; ob = t;
            __syncthreads();
        }
    }
}

// ---------------- mma.sync bf16 Jacobian kernel (R8 compute + double-buffered B) ----------------
// CTA b: samples 2b, 2b+1 (M=128). GEMM1: Bt = A1(masked W3) @ W2 ; A2 = bf16(mask_m1(Bt));
// GEMM2: H = A2 @ W1 ; q_s = ||H_s||^2 ; out = tanh(softplus(k) f / (sqrt(q)+1e-4)).
// 4 k128 B chunks, ping-pong buffers, cp.async prefetch overlapping compute.
#define AS_ST 264
#define BS_ST 136
#define AS_OFF 0
#define B0_OFF 67584
#define B1_OFF 137216
#define MS_OFF 206848
#define JAC_SMEM 207104

__global__ void __launch_bounds__(256, 1)
jacmma_kernel(const float* __restrict__ kp, float* __restrict__ out)
{
    extern __shared__ char smc[];
    __nv_bfloat16* As = (__nv_bfloat16*)(smc + AS_OFF);
    __nv_bfloat16* Bb0 = (__nv_bfloat16*)(smc + B0_OFF);
    __nv_bfloat16* Bb1 = (__nv_bfloat16*)(smc + B1_OFF);
    unsigned* m1w = (unsigned*)(smc + MS_OFF);
    unsigned* m2w = m1w + 16;
    float* red = (float*)(m2w + 16);
    float* qv  = red + 8;

    const int tid = threadIdx.x;
    const int w = tid >> 5, lane = tid & 31;
    const int g = lane >> 2, tg = lane & 3;
    const int b = blockIdx.x;
    const int mw = (w >> 2) * 64, nw = (w & 3) * 64;
    const int s = w >> 2;

    if (tid < 16) {
        m1w[tid] = g_m1[(size_t)(2 * b + (tid >> 3)) * 8 + (tid & 7)];
        m2w[tid] = g_m2[(size_t)(2 * b + (tid >> 3)) * 8 + (tid & 7)];
    }

    // stage one k128 chunk of a B table into a buffer (R8 staging pattern)
    auto stageB = [&](const __nv_bfloat16* tab, int kc, __nv_bfloat16* dstBuf) {
        const char* src = (const char*)(tab + (size_t)tid * 256 + kc * 128);
        uint32_t dst = smem_u32(dstBuf) + (uint32_t)(tid * BS_ST) * 2;
        #pragma unroll
        for (int u2 = 0; u2 < 16; u2++)
            CP_ASYNC16(dst + u2 * 16, src + u2 * 16);
        CP_COMMIT();
    };

    stageB(g_B1T, 0, Bb0);
    stageB(g_B1T, 1, Bb1);

    // ---- A1 = masked bf16(W3) (overlaps chunk0/1 flight) ----
    for (int u = tid; u < 16384; u += 256) {
        int m = u >> 7, i = (u & 127) * 2;
        int ss = m >> 6, o = m & 63;
        unsigned bits = (m2w[ss * 8 + (i >> 5)] >> (i & 31)) & 3u;
        unsigned v = *(const unsigned*)&g_A1b[o * 256 + i];
        if (!(bits & 1)) v &= 0xFFFF0000u;
        if (!(bits & 2)) v &= 0x0000FFFFu;
        *(unsigned*)&As[m * AS_ST + i] = v;
    }

    float c[4][8][4];
    #pragma unroll
    for (int mt = 0; mt < 4; mt++)
        #pragma unroll
        for (int nt = 0; nt < 8; nt++)
            #pragma unroll
            for (int e = 0; e < 4; e++) c[mt][nt][e] = 0.f;

    // R8's exact scalar-LDS compute loop over one k128 chunk
    auto compute = [&](const __nv_bfloat16* Bs, int kc) {
        #pragma unroll
        for (int ks = 0; ks < 8; ks++) {
            const int kk = ks * 16;
            uint32_t bf[8][2];
            #pragma unroll
            for (int nt = 0; nt < 8; nt++) {
                const __nv_bfloat16* bp = &Bs[(nw + nt * 8 + g) * BS_ST + kk + tg * 2];
                bf[nt][0] = *(const uint32_t*)bp;
                bf[nt][1] = *(const uint32_t*)(bp + 8);
            }
            #pragma unroll
            for (int mt = 0; mt < 4; mt++) {
                const __nv_bfloat16* ap = &As[(mw + mt * 16 + g) * AS_ST + kc * 128 + kk + tg * 2];
                uint32_t a0 = *(const uint32_t*)ap;
                uint32_t a1 = *(const uint32_t*)(ap + 8 * AS_ST);
                uint32_t a2 = *(const uint32_t*)(ap + 8);
                uint32_t a3 = *(const uint32_t*)(ap + 8 * AS_ST + 8);
                #pragma unroll
                for (int nt = 0; nt < 8; nt++)
                    mma_bf16(c[mt][nt], a0, a1, a2, a3, bf[nt][0], bf[nt][1]);
            }
        }
    };

    // ================== GEMM1 ==================
    CP_WAIT(1);
    __syncthreads();               // chunk0 ready; A1 visible
    compute(Bb0, 0);
    __syncthreads();               // Bb0 free
    stageB(g_B2T, 0, Bb0);         // prefetch GEMM2 k-low
    CP_WAIT(1);
    __syncthreads();               // chunk1 ready
    compute(Bb1, 1);
    __syncthreads();               // Bb1 free; GEMM1 accums final
    stageB(g_B2T, 1, Bb1);         // prefetch GEMM2 k-high

    // ---- A2 = bf16(mask_m1(Bt)) -> As (overlaps chunk3 flight) ----
    #pragma unroll
    for (int mt = 0; mt < 4; mt++) {
        const int r0 = mw + mt * 16 + g;
        #pragma unroll
        for (int nt = 0; nt < 8; nt++) {
            const int j0 = nw + nt * 8 + tg * 2;
            const unsigned word = m1w[s * 8 + (j0 >> 5)];
            const bool k0 = (word >> (j0 & 31)) & 1u;
            const bool k1 = (word >> ((j0 & 31) + 1)) & 1u;
            float* cc = c[mt][nt];
            unsigned lo0 = (unsigned)__bfloat16_as_ushort(__float2bfloat16(k0 ? cc[0] : 0.f));
            unsigned hi0 = (unsigned)__bfloat16_as_ushort(__float2bfloat16(k1 ? cc[1] : 0.f));
            *(unsigned*)&As[r0 * AS_ST + j0] = lo0 | (hi0 << 16);
            unsigned lo1 = (unsigned)__bfloat16_as_ushort(__float2bfloat16(k0 ? cc[2] : 0.f));
            unsigned hi1 = (unsigned)__bfloat16_as_ushort(__float2bfloat16(k1 ? cc[3] : 0.f));
            *(unsigned*)&As[(r0 + 8) * AS_ST + j0] = lo1 | (hi1 << 16);
        }
    }
    #pragma unroll
    for (int mt = 0; mt < 4; mt++)
        #pragma unroll
        for (int nt = 0; nt < 8; nt++)
            #pragma unroll
            for (int e = 0; e < 4; e++) c[mt][nt][e] = 0.f;

    // ================== GEMM2 ==================
    CP_WAIT(1);
    __syncthreads();               // chunk2 ready; A2 visible
    compute(Bb0, 0);
    CP_WAIT(0);
    __syncthreads();               // chunk3 ready
    compute(Bb1, 1);

    // ---- q reduction ----
    float q = 0.f;
    #pragma unroll
    for (int mt = 0; mt < 4; mt++)
        #pragma unroll
        for (int nt = 0; nt < 8; nt++)
            #pragma unroll
            for (int e = 0; e < 4; e++)
                q = fmaf(c[mt][nt][e], c[mt][nt][e], q);
    #pragma unroll
    for (int sft = 16; sft; sft >>= 1) q += __shfl_xor_sync(0xFFFFFFFFu, q, sft);
    if (lane == 0) red[w] = q;
    __syncthreads();
    if (tid < 2)
        qv[tid] = red[tid * 4] + red[tid * 4 + 1] + red[tid * 4 + 2] + red[tid * 4 + 3];
    __syncthreads();
    if (tid < 128) {
        int ss = tid >> 6, o = tid & 63;
        float fv = g_f[(size_t)(2 * b + ss) * 64 + o];
        float kk = kp[0];
        float sp = (kk > 20.f) ? kk : log1pf(expf(kk));
        out[(size_t)(2 * b + ss) * 64 + o] = tanhf(sp * fv / (sqrtf(qv[ss]) + 1e-4f));
    }
}

extern "C" void kernel_launch(void* const* d_in, const int* in_sizes, int n_in,
                              void* d_out, int out_size) {
    const float* x  = (const float*)d_in[0];
    const float* W1 = (const float*)d_in[1];
    const float* b1 = (const float*)d_in[2];
    const float* W2 = (const float*)d_in[3];
    const float* b2 = (const float*)d_in[4];
    const float* W3 = (const float*)d_in[5];
    const float* b3 = (const float*)d_in[6];
    const float* k  = (const float*)d_in[7];
    float* out = (float*)d_out;

    const size_t sm_fwd = 3 * 64 * FST * sizeof(float);
    cudaFuncSetAttribute(fwd_kernel, cudaFuncAttributeMaxDynamicSharedMemorySize, (int)sm_fwd);
    cudaFuncSetAttribute(jacmma_kernel, cudaFuncAttributeMaxDynamicSharedMemorySize, JAC_SMEM);

    prep_kernel<<<64, 256>>>(W1, W2, W3);
    fwd_kernel<<<128, 256, sm_fwd>>>(x, W1, b1, W2, b2, W3, b3);
    jacmma_kernel<<<NB / 2, 256, JAC_SMEM>>>(k, out);
}